// round 6
// baseline (speedup 1.0000x reference)
#include <cuda_runtime.h>
#include <cuda_bf16.h>
#include <cstdint>

#define N_ELEC 8192
#define N_NUC  512
#define EMB    256
#define KER    256
#define DF     64
#define MID    128
#define NEDGE  131072
#define TILE_M 128
#define NTILES (NEDGE / TILE_M)

// ---------------- device scratch (no allocations allowed) ----------------
__device__ float g_H[N_ELEC * KER];                 // electrons @ h_w
__device__ float g_Z[(size_t)N_ELEC * 3 * KER];     // [z_same | z_anti | z_n] per row
__device__ float g_WEH[(size_t)NEDGE * KER];        // per-edge messages (reused per type)
__device__ __nv_bfloat16 g_w1img[3][2][DF * MID];   // [type][hi/lo] row-major [k][n]
__device__ __nv_bfloat16 g_w2img[3][2][MID * KER];  // [type][hi/lo] row-major [k][n]
__device__ __nv_bfloat16 g_hws[2][EMB * KER];       // h_w split  [k][n]
__device__ __nv_bfloat16 g_gcs[2][3 * KER * EMB];   // gcat split [k][n], rows: g0|g1|g2
// CSR
__device__ int g_cnt[3][N_ELEC];
__device__ int g_off[3][N_ELEC + 1];
__device__ int g_cur[3][N_ELEC];
__device__ int g_lst[3][NEDGE];

// ---------------- helpers ----------------
__device__ __forceinline__ uint32_t smem_u32(const void* p) {
    uint32_t a;
    asm("{ .reg .u64 t; cvta.to.shared.u64 t, %1; cvt.u32.u64 %0, t; }" : "=r"(a) : "l"(p));
    return a;
}
__device__ __forceinline__ void ldsm4(uint32_t (&r)[4], uint32_t addr) {
    asm volatile("ldmatrix.sync.aligned.m8n8.x4.shared.b16 {%0,%1,%2,%3}, [%4];"
                 : "=r"(r[0]), "=r"(r[1]), "=r"(r[2]), "=r"(r[3]) : "r"(addr));
}
__device__ __forceinline__ void ldsm4t(uint32_t (&r)[4], uint32_t addr) {
    asm volatile("ldmatrix.sync.aligned.m8n8.x4.trans.shared.b16 {%0,%1,%2,%3}, [%4];"
                 : "=r"(r[0]), "=r"(r[1]), "=r"(r[2]), "=r"(r[3]) : "r"(addr));
}
__device__ __forceinline__ void mma16816(float (&d)[4], const uint32_t (&a)[4],
                                         uint32_t b0, uint32_t b1) {
    asm volatile("mma.sync.aligned.m16n8k16.row.col.f32.bf16.bf16.f32 "
                 "{%0,%1,%2,%3},{%4,%5,%6,%7},{%8,%9},{%0,%1,%2,%3};"
                 : "+f"(d[0]), "+f"(d[1]), "+f"(d[2]), "+f"(d[3])
                 : "r"(a[0]), "r"(a[1]), "r"(a[2]), "r"(a[3]), "r"(b0), "r"(b1));
}
__device__ __forceinline__ float ssp(float x) {
    float t = __expf(-fabsf(x));
    return fmaxf(x, 0.0f) + __logf(1.0f + t) - 0.6931471805599453f;
}
__device__ __forceinline__ uint32_t pkbf(__nv_bfloat16 a, __nv_bfloat16 b) {
    return (uint32_t)__bfloat16_as_ushort(a) | ((uint32_t)__bfloat16_as_ushort(b) << 16);
}

// ---------------- weight prep: bf16 hi/lo split, row-major [k][n] ----------------
__global__ void prep_kernel(const float* w1_0, const float* w1_1, const float* w1_2,
                            const float* w2_0, const float* w2_1, const float* w2_2,
                            const float* hw, const float* g0, const float* g1,
                            const float* g2) {
    const float* w1p[3] = {w1_0, w1_1, w1_2};
    const float* w2p[3] = {w2_0, w2_1, w2_2};
    const int stride = gridDim.x * blockDim.x;
    const int t0 = blockIdx.x * blockDim.x + threadIdx.x;
    for (int i = t0; i < 3 * DF * MID; i += stride) {
        int t = i / (DF * MID), e = i % (DF * MID);
        float v = w1p[t][e];
        __nv_bfloat16 hi = __float2bfloat16(v);
        g_w1img[t][0][e] = hi;
        g_w1img[t][1][e] = __float2bfloat16(v - __bfloat162float(hi));
    }
    for (int i = t0; i < 3 * MID * KER; i += stride) {
        int t = i / (MID * KER), e = i % (MID * KER);
        float v = w2p[t][e];
        __nv_bfloat16 hi = __float2bfloat16(v);
        g_w2img[t][0][e] = hi;
        g_w2img[t][1][e] = __float2bfloat16(v - __bfloat162float(hi));
    }
    for (int i = t0; i < EMB * KER; i += stride) {
        float v = hw[i];
        __nv_bfloat16 hi = __float2bfloat16(v);
        g_hws[0][i] = hi;
        g_hws[1][i] = __float2bfloat16(v - __bfloat162float(hi));
    }
    for (int i = t0; i < 3 * KER * EMB; i += stride) {
        int t = i / (KER * EMB), e = i % (KER * EMB);
        float v = (t == 0 ? g0 : (t == 1 ? g1 : g2))[e];
        __nv_bfloat16 hi = __float2bfloat16(v);
        g_gcs[0][i] = hi;
        g_gcs[1][i] = __float2bfloat16(v - __bfloat162float(hi));
    }
}

// ---------------- CSR build ----------------
__global__ void hist_kernel(const int* r0, const int* r1, const int* r2) {
    const int* rp[3] = {r0, r1, r2};
    const int stride = gridDim.x * blockDim.x;
    for (int i = blockIdx.x * blockDim.x + threadIdx.x; i < 3 * NEDGE; i += stride) {
        int t = i >> 17, e = i & (NEDGE - 1);
        atomicAdd(&g_cnt[t][rp[t][e]], 1);
    }
}
__global__ void __launch_bounds__(1024) scan_kernel() {
    __shared__ int part[1024];
    const int t = blockIdx.x, tid = threadIdx.x;
    const int base = tid * 8;
    int loc[8], s = 0;
    #pragma unroll
    for (int i = 0; i < 8; i++) { loc[i] = s; s += g_cnt[t][base + i]; }
    part[tid] = s;
    __syncthreads();
    for (int ofs = 1; ofs < 1024; ofs <<= 1) {
        int v = (tid >= ofs) ? part[tid - ofs] : 0;
        __syncthreads();
        part[tid] += v;
        __syncthreads();
    }
    int prefix = (tid == 0) ? 0 : part[tid - 1];
    #pragma unroll
    for (int i = 0; i < 8; i++) {
        g_off[t][base + i] = prefix + loc[i];
        g_cur[t][base + i] = prefix + loc[i];
    }
    if (tid == 1023) g_off[t][N_ELEC] = part[1023];
}
__global__ void fill_kernel(const int* r0, const int* r1, const int* r2) {
    const int* rp[3] = {r0, r1, r2};
    const int stride = gridDim.x * blockDim.x;
    for (int i = blockIdx.x * blockDim.x + threadIdx.x; i < 3 * NEDGE; i += stride) {
        int t = i >> 17, e = i & (NEDGE - 1);
        int pos = atomicAdd(&g_cur[t][rp[t][e]], 1);
        g_lst[t][pos] = e;
    }
}
__global__ void sort_kernel() {
    int idx = blockIdx.x * blockDim.x + threadIdx.x;
    if (idx >= 3 * N_ELEC) return;
    int t = idx >> 13, r = idx & (N_ELEC - 1);
    int s = g_off[t][r], e = g_off[t][r + 1];
    int n = e - s;
    if (n <= 1) return;
    if (n > 64) n = 64;
    int buf[64];
    for (int i = 0; i < n; i++) buf[i] = g_lst[t][s + i];
    for (int i = 1; i < n; i++) {
        int v = buf[i], j = i - 1;
        while (j >= 0 && buf[j] > v) { buf[j + 1] = buf[j]; j--; }
        buf[j + 1] = v;
    }
    for (int i = 0; i < n; i++) g_lst[t][s + i] = buf[i];
}

// ---------------- smem byte offsets (padded rows for conflict-free ldmatrix) ----
#define SO_B1  0
#define SO_DH  512
#define SO_DL  (SO_DH + 18432)
#define SO_W1H (SO_DL + 18432)
#define SO_W1L (SO_W1H + 17408)
#define SO_W2H (SO_W1L + 17408)
#define SO_W2L (SO_W2H + 67584)
#define EDGE_SMEM (SO_W2L + 67584)      // 207360 B

// ---------------- fused edge kernel (mma.sync bf16 split, 512 threads) ----------
// Produces WEH[e][c] = we[e][c] * src[snd[e]][c]   (plain coalesced-ish STG)
__global__ void __launch_bounds__(512, 1)
edge_mma(const float* __restrict__ dist, const float* __restrict__ b1g,
         const float* __restrict__ src, const int* __restrict__ snd,
         float* __restrict__ WEH, int type)
{
    extern __shared__ __align__(16) char smem[];
    const uint32_t sb = smem_u32(smem);
    const int tid = threadIdx.x, wid = tid >> 5, l = tid & 31;
    const int rg = wid >> 1, nh = wid & 1;   // 8 row-groups x 2 N-halves

    // ---- stage weights + bias (persistent) ----
    {
        const uint4* w1g = (const uint4*)&g_w1img[type][0][0];
        for (int i = tid; i < 2048; i += 512) {
            int sp = i >> 10, idx = i & 1023;
            int row = idx >> 4, ch = idx & 15;
            *(uint4*)(smem + (sp ? SO_W1L : SO_W1H) + row * 272 + ch * 16) =
                w1g[sp * 1024 + idx];
        }
        const uint4* w2g = (const uint4*)&g_w2img[type][0][0];
        for (int i = tid; i < 8192; i += 512) {
            int sp = i >> 12, idx = i & 4095;
            int row = idx >> 5, ch = idx & 31;
            *(uint4*)(smem + (sp ? SO_W2L : SO_W2H) + row * 528 + ch * 16) =
                w2g[sp * 4096 + idx];
        }
        if (tid < MID) ((float*)(smem + SO_B1))[tid] = b1g[tid];
    }
    __syncthreads();

    const float* b1s = (const float*)(smem + SO_B1);
    const uint32_t lrow = (uint32_t)(l & 15), lc8 = (uint32_t)((l >> 4) << 3);
    const uint32_t daH = sb + SO_DH + ((rg * 16 + lrow) * 72 + lc8) * 2;
    const uint32_t daL = daH + (SO_DL - SO_DH);
    const uint32_t w1H = sb + SO_W1H + (lrow * 136 + lc8) * 2;
    const uint32_t w1L = w1H + (SO_W1L - SO_W1H);
    const uint32_t w2H = sb + SO_W2H + (lrow * 264 + lc8) * 2;
    const uint32_t w2L = w2H + (SO_W2L - SO_W2H);

    for (int tile = blockIdx.x; tile < NTILES; tile += 148) {
        // ---- stage dist tile: split f32 -> bf16 hi/lo into padded smem ----
        const float4* dsrc = (const float4*)(dist + (size_t)tile * TILE_M * DF);
        for (int i = tid; i < 2048; i += 512) {
            float4 v = dsrc[i];
            int row = i >> 4, c4 = (i & 15) << 2;
            __nv_bfloat16 h0 = __float2bfloat16(v.x), h1 = __float2bfloat16(v.y);
            __nv_bfloat16 h2 = __float2bfloat16(v.z), h3 = __float2bfloat16(v.w);
            uint32_t off = (uint32_t)(row * 72 + c4) * 2;
            *(uint2*)(smem + SO_DH + off) = make_uint2(pkbf(h0, h1), pkbf(h2, h3));
            *(uint2*)(smem + SO_DL + off) = make_uint2(
                pkbf(__float2bfloat16(v.x - __bfloat162float(h0)),
                     __float2bfloat16(v.y - __bfloat162float(h1))),
                pkbf(__float2bfloat16(v.z - __bfloat162float(h2)),
                     __float2bfloat16(v.w - __bfloat162float(h3))));
        }
        __syncthreads();

        // ---- stage1 (duplicated per N-half partner): mid = ssp(dist@w1+b1), 2 passes
        uint32_t mAh[8][4], mAl[8][4];
        #pragma unroll
        for (int pass = 0; pass < 2; pass++) {
            float acc1[8][4];
            #pragma unroll
            for (int j = 0; j < 8; j++)
                #pragma unroll
                for (int c = 0; c < 4; c++) acc1[j][c] = 0.0f;
            #pragma unroll
            for (int kt = 0; kt < 4; kt++) {
                uint32_t Ah[4], Al[4];
                ldsm4(Ah, daH + kt * 32);
                ldsm4(Al, daL + kt * 32);
                #pragma unroll
                for (int nc = 0; nc < 4; nc++) {
                    const uint32_t nb = (uint32_t)(pass * 64 + nc * 16) * 2;
                    uint32_t bh[4], bl[4];
                    ldsm4t(bh, w1H + kt * 4352 + nb);
                    ldsm4t(bl, w1L + kt * 4352 + nb);
                    mma16816(acc1[2 * nc],     Ah, bh[0], bh[1]);
                    mma16816(acc1[2 * nc + 1], Ah, bh[2], bh[3]);
                    mma16816(acc1[2 * nc],     Ah, bl[0], bl[1]);
                    mma16816(acc1[2 * nc + 1], Ah, bl[2], bl[3]);
                    mma16816(acc1[2 * nc],     Al, bh[0], bh[1]);
                    mma16816(acc1[2 * nc + 1], Al, bh[2], bh[3]);
                }
            }
            #pragma unroll
            for (int j = 0; j < 8; j++) {
                float2 bv = *(const float2*)&b1s[pass * 64 + 8 * j + 2 * (l & 3)];
                float v0 = ssp(acc1[j][0] + bv.x), v1 = ssp(acc1[j][1] + bv.y);
                float v2 = ssp(acc1[j][2] + bv.x), v3 = ssp(acc1[j][3] + bv.y);
                __nv_bfloat16 h0 = __float2bfloat16(v0), h1 = __float2bfloat16(v1);
                __nv_bfloat16 h2 = __float2bfloat16(v2), h3 = __float2bfloat16(v3);
                uint32_t ph01 = pkbf(h0, h1), ph23 = pkbf(h2, h3);
                uint32_t pl01 = pkbf(__float2bfloat16(v0 - __bfloat162float(h0)),
                                     __float2bfloat16(v1 - __bfloat162float(h1)));
                uint32_t pl23 = pkbf(__float2bfloat16(v2 - __bfloat162float(h2)),
                                     __float2bfloat16(v3 - __bfloat162float(h3)));
                const int kt = pass * 4 + (j >> 1);
                if ((j & 1) == 0) {
                    mAh[kt][0] = ph01; mAh[kt][1] = ph23;
                    mAl[kt][0] = pl01; mAl[kt][1] = pl23;
                } else {
                    mAh[kt][2] = ph01; mAh[kt][3] = ph23;
                    mAl[kt][2] = pl01; mAl[kt][3] = pl23;
                }
            }
        }

        // ---- stage2 + store: this warp's 128-col half, four 32-col chunks ----
        const int eidx = tile * TILE_M + rg * 16 + (l >> 2) + ((l & 1) << 3);
        const int s = __ldg(&snd[eidx]);
        const float* hrow = src + (size_t)s * KER;
        float* wrow = WEH + (size_t)eidx * KER;

        #pragma unroll
        for (int ct = 0; ct < 4; ct++) {
            const int colbase = nh * 128 + ct * 32;
            float acc2[4][4];
            #pragma unroll
            for (int j = 0; j < 4; j++)
                #pragma unroll
                for (int c = 0; c < 4; c++) acc2[j][c] = 0.0f;
            #pragma unroll
            for (int kt = 0; kt < 8; kt++) {
                #pragma unroll
                for (int nc = 0; nc < 2; nc++) {
                    const uint32_t nb = (uint32_t)(colbase + nc * 16) * 2;
                    uint32_t bh[4], bl[4];
                    ldsm4t(bh, w2H + kt * 8448 + nb);
                    ldsm4t(bl, w2L + kt * 8448 + nb);
                    mma16816(acc2[2 * nc],     mAh[kt], bh[0], bh[1]);
                    mma16816(acc2[2 * nc + 1], mAh[kt], bh[2], bh[3]);
                    mma16816(acc2[2 * nc],     mAh[kt], bl[0], bl[1]);
                    mma16816(acc2[2 * nc + 1], mAh[kt], bl[2], bl[3]);
                    mma16816(acc2[2 * nc],     mAl[kt], bh[0], bh[1]);
                    mma16816(acc2[2 * nc + 1], mAl[kt], bh[2], bh[3]);
                }
            }
            #pragma unroll
            for (int j = 0; j < 4; j++) {
                float x0 = __shfl_xor_sync(0xFFFFFFFFu, acc2[j][0], 1);
                float x1 = __shfl_xor_sync(0xFFFFFFFFu, acc2[j][1], 1);
                float x2 = __shfl_xor_sync(0xFFFFFFFFu, acc2[j][2], 1);
                float x3 = __shfl_xor_sync(0xFFFFFFFFu, acc2[j][3], 1);
                int colg = colbase + 8 * j + ((l & 2) << 1);
                float w0, w1, w2, w3;
                if ((l & 1) == 0) { w0 = acc2[j][0]; w1 = acc2[j][1]; w2 = x0; w3 = x1; }
                else              { w0 = x2; w1 = x3; w2 = acc2[j][2]; w3 = acc2[j][3]; }
                float4 hv = *(const float4*)&hrow[colg];
                *(float4*)&wrow[colg] =
                    make_float4(w0 * hv.x, w1 * hv.y, w2 * hv.z, w3 * hv.w);
            }
        }
        __syncthreads();   // dist region safe to overwrite next tile
    }
}

// ---------------- gather kernel: Z[r] = sum over CSR edges of WEH[e] ----------
__global__ void __launch_bounds__(256)
gather_kernel(const float* __restrict__ WEH, const int* __restrict__ off,
              const int* __restrict__ lst, float* __restrict__ Z, int zofs)
{
    const int wid = threadIdx.x >> 5, l = threadIdx.x & 31;
    const int r = blockIdx.x * 8 + wid;
    const int s = off[r], e = off[r + 1];
    float4 a0 = make_float4(0.f, 0.f, 0.f, 0.f);
    float4 a1 = make_float4(0.f, 0.f, 0.f, 0.f);
    const int col = l * 8;
    for (int i = s; i < e; i++) {
        const float4* p = (const float4*)(WEH + (size_t)lst[i] * KER + col);
        float4 v0 = p[0], v1 = p[1];
        a0.x += v0.x; a0.y += v0.y; a0.z += v0.z; a0.w += v0.w;
        a1.x += v1.x; a1.y += v1.y; a1.z += v1.z; a1.w += v1.w;
    }
    float* zp = Z + (size_t)r * 768 + zofs + col;
    *(float4*)zp = a0;
    *(float4*)(zp + 4) = a1;
}

// ---------------- HMMA bf16-split GEMM ----------------
#define GA_H 0
#define GA_L 18432
#define GB_H 36864
#define GB_L (36864 + 17408)
#define GEMM_SMEM (GB_L + 17408)   // 71680

__global__ void __launch_bounds__(256, 2)
gemm_mma(const float* __restrict__ A, int K,
         const __nv_bfloat16* __restrict__ Bh, const __nv_bfloat16* __restrict__ Bl,
         const float* __restrict__ resid, float* __restrict__ C)
{
    extern __shared__ __align__(16) char smem[];
    const uint32_t sb = smem_u32(smem);
    const int tid = threadIdx.x, wid = tid >> 5, l = tid & 31;
    const int n0 = blockIdx.x * 128;
    const int m0 = blockIdx.y * 128;
    const int rg = wid;

    const uint32_t lrow = (uint32_t)(l & 15), lc8 = (uint32_t)((l >> 4) << 3);
    const uint32_t aAH = sb + GA_H + ((rg * 16 + lrow) * 72 + lc8) * 2;
    const uint32_t aAL = aAH + (GA_L - GA_H);
    const uint32_t aBH = sb + GB_H + (lrow * 136 + lc8) * 2;
    const uint32_t aBL = aBH + (GB_L - GB_H);

    float acc[16][4];
    #pragma unroll
    for (int j = 0; j < 16; j++)
        #pragma unroll
        for (int c = 0; c < 4; c++) acc[j][c] = 0.0f;

    for (int k0 = 0; k0 < K; k0 += 64) {
        for (int i = tid; i < 2048; i += 256) {
            int row = i >> 4, c4 = (i & 15) << 2;
            float4 v = *(const float4*)&A[(size_t)(m0 + row) * K + k0 + c4];
            __nv_bfloat16 h0 = __float2bfloat16(v.x), h1 = __float2bfloat16(v.y);
            __nv_bfloat16 h2 = __float2bfloat16(v.z), h3 = __float2bfloat16(v.w);
            uint32_t off = (uint32_t)(row * 72 + c4) * 2;
            *(uint2*)(smem + GA_H + off) = make_uint2(pkbf(h0, h1), pkbf(h2, h3));
            *(uint2*)(smem + GA_L + off) = make_uint2(
                pkbf(__float2bfloat16(v.x - __bfloat162float(h0)),
                     __float2bfloat16(v.y - __bfloat162float(h1))),
                pkbf(__float2bfloat16(v.z - __bfloat162float(h2)),
                     __float2bfloat16(v.w - __bfloat162float(h3))));
        }
        for (int i = tid; i < 2048; i += 256) {
            int r = i >> 5, cg = (i & 31);
            uint2 vh = *(const uint2*)&Bh[(size_t)(k0 + r) * 256 + n0 + cg * 4];
            uint2 vl = *(const uint2*)&Bl[(size_t)(k0 + r) * 256 + n0 + cg * 4];
            uint32_t off = (uint32_t)(r * 272 + cg * 8);
            *(uint2*)(smem + GB_H + off) = vh;
            *(uint2*)(smem + GB_L + off) = vl;
        }
        __syncthreads();
        #pragma unroll
        for (int kt = 0; kt < 4; kt++) {
            uint32_t Ah[4], Al[4];
            ldsm4(Ah, aAH + kt * 32);
            ldsm4(Al, aAL + kt * 32);
            #pragma unroll
            for (int nc = 0; nc < 8; nc++) {
                uint32_t bh[4], bl[4];
                ldsm4t(bh, aBH + kt * 4352 + nc * 32);
                ldsm4t(bl, aBL + kt * 4352 + nc * 32);
                mma16816(acc[2 * nc],     Ah, bh[0], bh[1]);
                mma16816(acc[2 * nc + 1], Ah, bh[2], bh[3]);
                mma16816(acc[2 * nc],     Ah, bl[0], bl[1]);
                mma16816(acc[2 * nc + 1], Ah, bl[2], bl[3]);
                mma16816(acc[2 * nc],     Al, bh[0], bh[1]);
                mma16816(acc[2 * nc + 1], Al, bh[2], bh[3]);
            }
        }
        __syncthreads();
    }

    const int row0 = m0 + rg * 16 + (l >> 2);
    const int colb = n0 + 2 * (l & 3);
    #pragma unroll
    for (int jn = 0; jn < 16; jn++) {
        const int col = colb + jn * 8;
        size_t o0 = (size_t)row0 * 256 + col;
        size_t o1 = (size_t)(row0 + 8) * 256 + col;
        float2 p0 = make_float2(acc[jn][0], acc[jn][1]);
        float2 p1 = make_float2(acc[jn][2], acc[jn][3]);
        if (resid) {
            float2 r0 = *(const float2*)&resid[o0];
            float2 r1 = *(const float2*)&resid[o1];
            p0.x += r0.x; p0.y += r0.y;
            p1.x += r1.x; p1.y += r1.y;
        }
        *(float2*)&C[o0] = p0;
        *(float2*)&C[o1] = p1;
    }
}

// ---------------- launch ----------------
extern "C" void kernel_launch(void* const* d_in, const int* in_sizes, int n_in,
                              void* d_out, int out_size)
{
    const float *electrons = nullptr, *nuclei = nullptr, *h_w = nullptr;
    const float *dist[3] = {0, 0, 0}, *w1[3] = {0, 0, 0}, *b1[3] = {0, 0, 0};
    const float *w2[3] = {0, 0, 0}, *g[3] = {0, 0, 0};
    const int* idx6[6] = {0, 0, 0, 0, 0, 0};
    int nd = 0, n1 = 0, nb = 0, n2 = 0, ng = 0, ni = 0;
    bool have_nuc = false;
    for (int i = 0; i < n_in; i++) {
        int s = in_sizes[i];
        const void* p = d_in[i];
        if (s == N_ELEC * EMB)        electrons = (const float*)p;
        else if (s == NEDGE * DF)     { if (nd < 3) dist[nd++] = (const float*)p; }
        else if (s == DF * MID)       { if (n1 < 3) w1[n1++] = (const float*)p; }
        else if (s == MID)            { if (nb < 3) b1[nb++] = (const float*)p; }
        else if (s == MID * KER)      { if (n2 < 3) w2[n2++] = (const float*)p; }
        else if (s == KER * EMB)      { if (ng < 3) g[ng++] = (const float*)p; else h_w = (const float*)p; }
        else if (s == NEDGE)          {  // 131072: nuclei (512*256) first, then 6 index arrays
            if (!have_nuc) { nuclei = (const float*)p; have_nuc = true; }
            else if (ni < 6) idx6[ni++] = (const int*)p;
        }
    }

    float *Hbuf = nullptr, *Zbuf = nullptr, *WEH = nullptr;
    cudaGetSymbolAddress((void**)&Hbuf, g_H);
    cudaGetSymbolAddress((void**)&Zbuf, g_Z);
    cudaGetSymbolAddress((void**)&WEH, g_WEH);
    __nv_bfloat16 *hws = nullptr, *gcs = nullptr;
    cudaGetSymbolAddress((void**)&hws, g_hws);
    cudaGetSymbolAddress((void**)&gcs, g_gcs);
    int *cnt = nullptr, *off = nullptr, *lst = nullptr;
    cudaGetSymbolAddress((void**)&cnt, g_cnt);
    cudaGetSymbolAddress((void**)&off, g_off);
    cudaGetSymbolAddress((void**)&lst, g_lst);

    cudaFuncSetAttribute(edge_mma, cudaFuncAttributeMaxDynamicSharedMemorySize, EDGE_SMEM);
    cudaFuncSetAttribute(gemm_mma, cudaFuncAttributeMaxDynamicSharedMemorySize, GEMM_SMEM);

    prep_kernel<<<256, 256>>>(w1[0], w1[1], w1[2], w2[0], w2[1], w2[2],
                              h_w, g[0], g[1], g[2]);

    // ---- CSR build (deterministic after per-bin sort) ----
    cudaMemsetAsync(cnt, 0, sizeof(int) * 3 * N_ELEC, 0);
    hist_kernel<<<256, 256>>>(idx6[3], idx6[4], idx6[5]);
    scan_kernel<<<3, 1024>>>();
    fill_kernel<<<256, 256>>>(idx6[3], idx6[4], idx6[5]);
    sort_kernel<<<(3 * N_ELEC + 255) / 256, 256>>>();

    dim3 ggrid(2, 64);
    // H = electrons @ h_w
    gemm_mma<<<ggrid, 256, GEMM_SMEM>>>(electrons, 256, hws, hws + EMB * KER,
                                        nullptr, Hbuf);

    const float* srcs[3] = { Hbuf, Hbuf, nuclei };
    for (int t = 0; t < 3; t++) {
        edge_mma<<<148, 512, EDGE_SMEM>>>(dist[t], b1[t], srcs[t], idx6[t], WEH, t);
        gather_kernel<<<N_ELEC / 8, 256>>>(WEH, off + t * (N_ELEC + 1),
                                           lst + t * NEDGE, Zbuf, t * 256);
    }

    // out = electrons + Zcat @ [g_same; g_anti; g_n]
    gemm_mma<<<ggrid, 256, GEMM_SMEM>>>(Zbuf, 768, gcs, gcs + 3 * KER * EMB,
                                        electrons, (float*)d_out);
}

// round 7
// speedup vs baseline: 1.2707x; 1.2707x over previous
#include <cuda_runtime.h>
#include <cuda_bf16.h>
#include <cstdint>

#define N_ELEC 8192
#define N_NUC  512
#define EMB    256
#define KER    256
#define DF     64
#define MID    128
#define NEDGE  131072
#define TILE_M 128
#define NTILES (NEDGE / TILE_M)

// ---------------- device scratch (no allocations allowed) ----------------
__device__ float g_H[N_ELEC * KER];                 // electrons @ h_w
__device__ float g_Z[(size_t)N_ELEC * 3 * KER];     // [z_same | z_anti | z_n] per row
__device__ __nv_bfloat16 g_w1img[3][2][DF * MID];   // [type][hi/lo] row-major [k][n]
__device__ __nv_bfloat16 g_w2img[3][2][MID * KER];  // [type][hi/lo] row-major [k][n]
__device__ __nv_bfloat16 g_hws[2][EMB * KER];       // h_w split  [k][n]
__device__ __nv_bfloat16 g_gcs[2][3 * KER * EMB];   // gcat split [k][n], rows: g0|g1|g2

// ---------------- helpers ----------------
__device__ __forceinline__ uint32_t smem_u32(const void* p) {
    uint32_t a;
    asm("{ .reg .u64 t; cvta.to.shared.u64 t, %1; cvt.u32.u64 %0, t; }" : "=r"(a) : "l"(p));
    return a;
}
__device__ __forceinline__ void ldsm4(uint32_t (&r)[4], uint32_t addr) {
    asm volatile("ldmatrix.sync.aligned.m8n8.x4.shared.b16 {%0,%1,%2,%3}, [%4];"
                 : "=r"(r[0]), "=r"(r[1]), "=r"(r[2]), "=r"(r[3]) : "r"(addr));
}
__device__ __forceinline__ void ldsm4t(uint32_t (&r)[4], uint32_t addr) {
    asm volatile("ldmatrix.sync.aligned.m8n8.x4.trans.shared.b16 {%0,%1,%2,%3}, [%4];"
                 : "=r"(r[0]), "=r"(r[1]), "=r"(r[2]), "=r"(r[3]) : "r"(addr));
}
__device__ __forceinline__ void mma16816(float (&d)[4], const uint32_t (&a)[4],
                                         uint32_t b0, uint32_t b1) {
    asm volatile("mma.sync.aligned.m16n8k16.row.col.f32.bf16.bf16.f32 "
                 "{%0,%1,%2,%3},{%4,%5,%6,%7},{%8,%9},{%0,%1,%2,%3};"
                 : "+f"(d[0]), "+f"(d[1]), "+f"(d[2]), "+f"(d[3])
                 : "r"(a[0]), "r"(a[1]), "r"(a[2]), "r"(a[3]), "r"(b0), "r"(b1));
}
__device__ __forceinline__ void red_add_v4(float* p, float x, float y, float z, float w) {
    asm volatile("red.global.add.v4.f32 [%0], {%1, %2, %3, %4};"
                 :: "l"(p), "f"(x), "f"(y), "f"(z), "f"(w) : "memory");
}
__device__ __forceinline__ float ssp(float x) {
    float t = __expf(-fabsf(x));
    return fmaxf(x, 0.0f) + __logf(1.0f + t) - 0.6931471805599453f;
}
__device__ __forceinline__ uint32_t pkbf(__nv_bfloat16 a, __nv_bfloat16 b) {
    return (uint32_t)__bfloat16_as_ushort(a) | ((uint32_t)__bfloat16_as_ushort(b) << 16);
}

// ---------------- weight prep: bf16 hi/lo split, row-major [k][n] ----------------
__global__ void prep_kernel(const float* w1_0, const float* w1_1, const float* w1_2,
                            const float* w2_0, const float* w2_1, const float* w2_2,
                            const float* hw, const float* g0, const float* g1,
                            const float* g2) {
    const float* w1p[3] = {w1_0, w1_1, w1_2};
    const float* w2p[3] = {w2_0, w2_1, w2_2};
    const int stride = gridDim.x * blockDim.x;
    const int t0 = blockIdx.x * blockDim.x + threadIdx.x;
    for (int i = t0; i < 3 * DF * MID; i += stride) {
        int t = i / (DF * MID), e = i % (DF * MID);
        float v = w1p[t][e];
        __nv_bfloat16 hi = __float2bfloat16(v);
        g_w1img[t][0][e] = hi;
        g_w1img[t][1][e] = __float2bfloat16(v - __bfloat162float(hi));
    }
    for (int i = t0; i < 3 * MID * KER; i += stride) {
        int t = i / (MID * KER), e = i % (MID * KER);
        float v = w2p[t][e];
        __nv_bfloat16 hi = __float2bfloat16(v);
        g_w2img[t][0][e] = hi;
        g_w2img[t][1][e] = __float2bfloat16(v - __bfloat162float(hi));
    }
    for (int i = t0; i < EMB * KER; i += stride) {
        float v = hw[i];
        __nv_bfloat16 hi = __float2bfloat16(v);
        g_hws[0][i] = hi;
        g_hws[1][i] = __float2bfloat16(v - __bfloat162float(hi));
    }
    for (int i = t0; i < 3 * KER * EMB; i += stride) {
        int t = i / (KER * EMB), e = i % (KER * EMB);
        float v = (t == 0 ? g0 : (t == 1 ? g1 : g2))[e];
        __nv_bfloat16 hi = __float2bfloat16(v);
        g_gcs[0][i] = hi;
        g_gcs[1][i] = __float2bfloat16(v - __bfloat162float(hi));
    }
}

// ---------------- smem byte offsets (padded rows for conflict-free ldmatrix) ----
#define SO_B1  0
#define SO_DH  512
#define SO_DL  (SO_DH + 18432)
#define SO_W1H (SO_DL + 18432)
#define SO_W1L (SO_W1H + 17408)
#define SO_W2H (SO_W1L + 17408)
#define SO_W2L (SO_W2H + 67584)
#define EDGE_SMEM (SO_W2L + 67584)      // 207360 B

struct EdgeParams {
    const float* dist[3];
    const float* b1[3];
    const float* src[3];
    const int*   snd[3];
    const int*   rcv[3];
    float*       Z;
};

// ---------------- fused edge kernel (mma.sync bf16 split, 512 threads) ----------
__global__ void __launch_bounds__(512, 1) edge_mma(EdgeParams P)
{
    extern __shared__ __align__(16) char smem[];
    const uint32_t sb = smem_u32(smem);
    const int tid = threadIdx.x, wid = tid >> 5, l = tid & 31;
    const int type = blockIdx.x % 3, cta = blockIdx.x / 3;
    const int rg = wid >> 1, nh = wid & 1;   // 8 row-groups x 2 N-halves

    // ---- stage weights + bias (persistent) ----
    {
        const uint4* w1g = (const uint4*)&g_w1img[type][0][0];
        for (int i = tid; i < 2048; i += 512) {
            int sp = i >> 10, idx = i & 1023;
            int row = idx >> 4, ch = idx & 15;
            *(uint4*)(smem + (sp ? SO_W1L : SO_W1H) + row * 272 + ch * 16) =
                w1g[sp * 1024 + idx];
        }
        const uint4* w2g = (const uint4*)&g_w2img[type][0][0];
        for (int i = tid; i < 8192; i += 512) {
            int sp = i >> 12, idx = i & 4095;
            int row = idx >> 5, ch = idx & 31;
            *(uint4*)(smem + (sp ? SO_W2L : SO_W2H) + row * 528 + ch * 16) =
                w2g[sp * 4096 + idx];
        }
        if (tid < MID) ((float*)(smem + SO_B1))[tid] = P.b1[type][tid];
    }
    __syncthreads();

    const float* b1s = (const float*)(smem + SO_B1);
    const uint32_t lrow = (uint32_t)(l & 15), lc8 = (uint32_t)((l >> 4) << 3);
    const uint32_t daH = sb + SO_DH + ((rg * 16 + lrow) * 72 + lc8) * 2;
    const uint32_t daL = daH + (SO_DL - SO_DH);
    const uint32_t w1H = sb + SO_W1H + (lrow * 136 + lc8) * 2;
    const uint32_t w1L = w1H + (SO_W1L - SO_W1H);
    const uint32_t w2H = sb + SO_W2H + (lrow * 264 + lc8) * 2;
    const uint32_t w2L = w2H + (SO_W2L - SO_W2H);

    const float* src = P.src[type];
    const int* snd = P.snd[type];
    const int* rcv = P.rcv[type];
    float* Z = P.Z;
    const int zofs = type * 256;
    const float4* dbase = (const float4*)P.dist[type];

    // ---- register prefetch of first dist tile ----
    float4 dreg[4];
    if (cta < NTILES) {
        #pragma unroll
        for (int q = 0; q < 4; q++)
            dreg[q] = dbase[(size_t)cta * 2048 + tid + q * 512];
    }

    for (int tile = cta; tile < NTILES; tile += 148) {
        // ---- write prefetched dist tile: split f32 -> bf16 hi/lo into padded smem
        #pragma unroll
        for (int q = 0; q < 4; q++) {
            const int i = tid + q * 512;
            float4 v = dreg[q];
            int row = i >> 4, c4 = (i & 15) << 2;
            __nv_bfloat16 h0 = __float2bfloat16(v.x), h1 = __float2bfloat16(v.y);
            __nv_bfloat16 h2 = __float2bfloat16(v.z), h3 = __float2bfloat16(v.w);
            uint32_t off = (uint32_t)(row * 72 + c4) * 2;
            *(uint2*)(smem + SO_DH + off) = make_uint2(pkbf(h0, h1), pkbf(h2, h3));
            *(uint2*)(smem + SO_DL + off) = make_uint2(
                pkbf(__float2bfloat16(v.x - __bfloat162float(h0)),
                     __float2bfloat16(v.y - __bfloat162float(h1))),
                pkbf(__float2bfloat16(v.z - __bfloat162float(h2)),
                     __float2bfloat16(v.w - __bfloat162float(h3))));
        }
        __syncthreads();

        // ---- issue next tile's loads (completes during compute) ----
        if (tile + 148 < NTILES) {
            #pragma unroll
            for (int q = 0; q < 4; q++)
                dreg[q] = dbase[(size_t)(tile + 148) * 2048 + tid + q * 512];
        }

        // ---- stage1 (per N-half partner): mid = ssp(dist@w1+b1), 2 passes ----
        uint32_t mAh[8][4], mAl[8][4];
        #pragma unroll
        for (int pass = 0; pass < 2; pass++) {
            float acc1[8][4];
            #pragma unroll
            for (int j = 0; j < 8; j++)
                #pragma unroll
                for (int c = 0; c < 4; c++) acc1[j][c] = 0.0f;
            #pragma unroll
            for (int kt = 0; kt < 4; kt++) {
                uint32_t Ah[4], Al[4];
                ldsm4(Ah, daH + kt * 32);
                ldsm4(Al, daL + kt * 32);
                #pragma unroll
                for (int nc = 0; nc < 4; nc++) {
                    const uint32_t nb = (uint32_t)(pass * 64 + nc * 16) * 2;
                    uint32_t bh[4], bl[4];
                    ldsm4t(bh, w1H + kt * 4352 + nb);
                    ldsm4t(bl, w1L + kt * 4352 + nb);
                    mma16816(acc1[2 * nc],     Ah, bh[0], bh[1]);
                    mma16816(acc1[2 * nc + 1], Ah, bh[2], bh[3]);
                    mma16816(acc1[2 * nc],     Ah, bl[0], bl[1]);
                    mma16816(acc1[2 * nc + 1], Ah, bl[2], bl[3]);
                    mma16816(acc1[2 * nc],     Al, bh[0], bh[1]);
                    mma16816(acc1[2 * nc + 1], Al, bh[2], bh[3]);
                }
            }
            #pragma unroll
            for (int j = 0; j < 8; j++) {
                float2 bv = *(const float2*)&b1s[pass * 64 + 8 * j + 2 * (l & 3)];
                float v0 = ssp(acc1[j][0] + bv.x), v1 = ssp(acc1[j][1] + bv.y);
                float v2 = ssp(acc1[j][2] + bv.x), v3 = ssp(acc1[j][3] + bv.y);
                __nv_bfloat16 h0 = __float2bfloat16(v0), h1 = __float2bfloat16(v1);
                __nv_bfloat16 h2 = __float2bfloat16(v2), h3 = __float2bfloat16(v3);
                uint32_t ph01 = pkbf(h0, h1), ph23 = pkbf(h2, h3);
                uint32_t pl01 = pkbf(__float2bfloat16(v0 - __bfloat162float(h0)),
                                     __float2bfloat16(v1 - __bfloat162float(h1)));
                uint32_t pl23 = pkbf(__float2bfloat16(v2 - __bfloat162float(h2)),
                                     __float2bfloat16(v3 - __bfloat162float(h3)));
                const int kt = pass * 4 + (j >> 1);
                if ((j & 1) == 0) {
                    mAh[kt][0] = ph01; mAh[kt][1] = ph23;
                    mAl[kt][0] = pl01; mAl[kt][1] = pl23;
                } else {
                    mAh[kt][2] = ph01; mAh[kt][3] = ph23;
                    mAl[kt][2] = pl01; mAl[kt][3] = pl23;
                }
            }
        }

        // ---- stage2 + scatter: this warp's 128-col half, four 32-col chunks ----
        const int eidx = tile * TILE_M + rg * 16 + (l >> 2) + ((l & 1) << 3);
        const int s  = __ldg(&snd[eidx]);
        const int rc = __ldg(&rcv[eidx]);
        const float* hrow = src + (size_t)s * KER;
        float* zrow = Z + (size_t)rc * 768 + zofs;

        #pragma unroll
        for (int ct = 0; ct < 4; ct++) {
            const int colbase = nh * 128 + ct * 32;
            float acch[4][4], accl[4][4];
            #pragma unroll
            for (int j = 0; j < 4; j++)
                #pragma unroll
                for (int c = 0; c < 4; c++) { acch[j][c] = 0.0f; accl[j][c] = 0.0f; }
            #pragma unroll
            for (int kt = 0; kt < 8; kt++) {
                #pragma unroll
                for (int nc = 0; nc < 2; nc++) {
                    const uint32_t nb = (uint32_t)(colbase + nc * 16) * 2;
                    uint32_t bh[4], bl[4];
                    ldsm4t(bh, w2H + kt * 8448 + nb);
                    ldsm4t(bl, w2L + kt * 8448 + nb);
                    mma16816(acch[2 * nc],     mAh[kt], bh[0], bh[1]);
                    mma16816(acch[2 * nc + 1], mAh[kt], bh[2], bh[3]);
                    mma16816(accl[2 * nc],     mAh[kt], bl[0], bl[1]);
                    mma16816(accl[2 * nc + 1], mAh[kt], bl[2], bl[3]);
                    mma16816(accl[2 * nc],     mAl[kt], bh[0], bh[1]);
                    mma16816(accl[2 * nc + 1], mAl[kt], bh[2], bh[3]);
                }
            }
            #pragma unroll
            for (int j = 0; j < 4; j++) {
                float c0 = acch[j][0] + accl[j][0];
                float c1 = acch[j][1] + accl[j][1];
                float c2 = acch[j][2] + accl[j][2];
                float c3 = acch[j][3] + accl[j][3];
                float x0 = __shfl_xor_sync(0xFFFFFFFFu, c0, 1);
                float x1 = __shfl_xor_sync(0xFFFFFFFFu, c1, 1);
                float x2 = __shfl_xor_sync(0xFFFFFFFFu, c2, 1);
                float x3 = __shfl_xor_sync(0xFFFFFFFFu, c3, 1);
                int colg = colbase + 8 * j + ((l & 2) << 1);
                float w0, w1, w2, w3;
                if ((l & 1) == 0) { w0 = c0; w1 = c1; w2 = x0; w3 = x1; }
                else              { w0 = x2; w1 = x3; w2 = c2; w3 = c3; }
                float4 hv = *(const float4*)&hrow[colg];
                red_add_v4(&zrow[colg], w0 * hv.x, w1 * hv.y, w2 * hv.z, w3 * hv.w);
            }
        }
        __syncthreads();   // dist region safe to overwrite next tile
    }
}

// ---------------- HMMA bf16-split GEMM: 128m x 64n tiles ----------------
#define QA_H 0
#define QA_L 18432
#define QB_H 36864
#define QB_L (36864 + 9216)
#define GEMM_SMEM (QB_L + 9216)   // 55296

__global__ void __launch_bounds__(256, 2)
gemm_mma(const float* __restrict__ A, int K,
         const __nv_bfloat16* __restrict__ Bh, const __nv_bfloat16* __restrict__ Bl,
         const float* __restrict__ resid, float* __restrict__ C)
{
    extern __shared__ __align__(16) char smem[];
    const uint32_t sb = smem_u32(smem);
    const int tid = threadIdx.x, wid = tid >> 5, l = tid & 31;
    const int n0 = blockIdx.x * 64;
    const int m0 = blockIdx.y * 128;
    const int rg = wid;

    const uint32_t lrow = (uint32_t)(l & 15), lc8 = (uint32_t)((l >> 4) << 3);
    const uint32_t aAH = sb + QA_H + ((rg * 16 + lrow) * 72 + lc8) * 2;
    const uint32_t aAL = aAH + (QA_L - QA_H);
    const uint32_t aBH = sb + QB_H + (lrow * 72 + lc8) * 2;
    const uint32_t aBL = aBH + (QB_L - QB_H);

    float acc[8][4];
    #pragma unroll
    for (int j = 0; j < 8; j++)
        #pragma unroll
        for (int c = 0; c < 4; c++) acc[j][c] = 0.0f;

    for (int k0 = 0; k0 < K; k0 += 64) {
        // stage A chunk [128][64] f32 -> bf16 hi/lo (stride 72 elems)
        for (int i = tid; i < 2048; i += 256) {
            int row = i >> 4, c4 = (i & 15) << 2;
            float4 v = *(const float4*)&A[(size_t)(m0 + row) * K + k0 + c4];
            __nv_bfloat16 h0 = __float2bfloat16(v.x), h1 = __float2bfloat16(v.y);
            __nv_bfloat16 h2 = __float2bfloat16(v.z), h3 = __float2bfloat16(v.w);
            uint32_t off = (uint32_t)(row * 72 + c4) * 2;
            *(uint2*)(smem + QA_H + off) = make_uint2(pkbf(h0, h1), pkbf(h2, h3));
            *(uint2*)(smem + QA_L + off) = make_uint2(
                pkbf(__float2bfloat16(v.x - __bfloat162float(h0)),
                     __float2bfloat16(v.y - __bfloat162float(h1))),
                pkbf(__float2bfloat16(v.z - __bfloat162float(h2)),
                     __float2bfloat16(v.w - __bfloat162float(h3))));
        }
        // stage B chunk [64 rows][64 cols] bf16 (stride 72 elems)
        for (int i = tid; i < 1024; i += 256) {
            int r = i >> 4, cg = (i & 15);
            uint2 vh = *(const uint2*)&Bh[(size_t)(k0 + r) * 256 + n0 + cg * 4];
            uint2 vl = *(const uint2*)&Bl[(size_t)(k0 + r) * 256 + n0 + cg * 4];
            uint32_t off = (uint32_t)(r * 144 + cg * 8);
            *(uint2*)(smem + QB_H + off) = vh;
            *(uint2*)(smem + QB_L + off) = vl;
        }
        __syncthreads();
        #pragma unroll
        for (int kt = 0; kt < 4; kt++) {
            uint32_t Ah[4], Al[4];
            ldsm4(Ah, aAH + kt * 32);
            ldsm4(Al, aAL + kt * 32);
            #pragma unroll
            for (int nc = 0; nc < 4; nc++) {
                uint32_t bh[4], bl[4];
                ldsm4t(bh, aBH + kt * 2304 + nc * 32);
                ldsm4t(bl, aBL + kt * 2304 + nc * 32);
                mma16816(acc[2 * nc],     Ah, bh[0], bh[1]);
                mma16816(acc[2 * nc + 1], Ah, bh[2], bh[3]);
                mma16816(acc[2 * nc],     Ah, bl[0], bl[1]);
                mma16816(acc[2 * nc + 1], Ah, bl[2], bl[3]);
                mma16816(acc[2 * nc],     Al, bh[0], bh[1]);
                mma16816(acc[2 * nc + 1], Al, bh[2], bh[3]);
            }
        }
        __syncthreads();
    }

    const int row0 = m0 + rg * 16 + (l >> 2);
    const int colb = n0 + 2 * (l & 3);
    #pragma unroll
    for (int jn = 0; jn < 8; jn++) {
        const int col = colb + jn * 8;
        size_t o0 = (size_t)row0 * 256 + col;
        size_t o1 = (size_t)(row0 + 8) * 256 + col;
        float2 p0 = make_float2(acc[jn][0], acc[jn][1]);
        float2 p1 = make_float2(acc[jn][2], acc[jn][3]);
        if (resid) {
            float2 r0 = *(const float2*)&resid[o0];
            float2 r1 = *(const float2*)&resid[o1];
            p0.x += r0.x; p0.y += r0.y;
            p1.x += r1.x; p1.y += r1.y;
        }
        *(float2*)&C[o0] = p0;
        *(float2*)&C[o1] = p1;
    }
}

// ---------------- launch ----------------
extern "C" void kernel_launch(void* const* d_in, const int* in_sizes, int n_in,
                              void* d_out, int out_size)
{
    const float *electrons = nullptr, *nuclei = nullptr, *h_w = nullptr;
    const float *dist[3] = {0, 0, 0}, *w1[3] = {0, 0, 0}, *b1[3] = {0, 0, 0};
    const float *w2[3] = {0, 0, 0}, *g[3] = {0, 0, 0};
    const int* idx6[6] = {0, 0, 0, 0, 0, 0};
    int nd = 0, n1 = 0, nb = 0, n2 = 0, ng = 0, ni = 0;
    bool have_nuc = false;
    for (int i = 0; i < n_in; i++) {
        int s = in_sizes[i];
        const void* p = d_in[i];
        if (s == N_ELEC * EMB)        electrons = (const float*)p;
        else if (s == NEDGE * DF)     { if (nd < 3) dist[nd++] = (const float*)p; }
        else if (s == DF * MID)       { if (n1 < 3) w1[n1++] = (const float*)p; }
        else if (s == MID)            { if (nb < 3) b1[nb++] = (const float*)p; }
        else if (s == MID * KER)      { if (n2 < 3) w2[n2++] = (const float*)p; }
        else if (s == KER * EMB)      { if (ng < 3) g[ng++] = (const float*)p; else h_w = (const float*)p; }
        else if (s == NEDGE)          {  // 131072: nuclei (512*256) first, then 6 index arrays
            if (!have_nuc) { nuclei = (const float*)p; have_nuc = true; }
            else if (ni < 6) idx6[ni++] = (const int*)p;
        }
    }

    float *Hbuf = nullptr, *Zbuf = nullptr;
    cudaGetSymbolAddress((void**)&Hbuf, g_H);
    cudaGetSymbolAddress((void**)&Zbuf, g_Z);
    __nv_bfloat16 *hws = nullptr, *gcs = nullptr;
    cudaGetSymbolAddress((void**)&hws, g_hws);
    cudaGetSymbolAddress((void**)&gcs, g_gcs);

    cudaFuncSetAttribute(edge_mma, cudaFuncAttributeMaxDynamicSharedMemorySize, EDGE_SMEM);
    cudaFuncSetAttribute(gemm_mma, cudaFuncAttributeMaxDynamicSharedMemorySize, GEMM_SMEM);

    prep_kernel<<<256, 256>>>(w1[0], w1[1], w1[2], w2[0], w2[1], w2[2],
                              h_w, g[0], g[1], g[2]);
    cudaMemsetAsync(Zbuf, 0, sizeof(float) * (size_t)N_ELEC * 3 * KER, 0);

    // H = electrons @ h_w   (grid 4x64 = 256 CTAs)
    gemm_mma<<<dim3(4, 64), 256, GEMM_SMEM>>>(electrons, 256, hws, hws + EMB * KER,
                                              nullptr, Hbuf);

    EdgeParams P;
    for (int t = 0; t < 3; t++) {
        P.dist[t] = dist[t];
        P.b1[t] = b1[t];
        P.snd[t] = idx6[t];
        P.rcv[t] = idx6[3 + t];
    }
    P.src[0] = Hbuf; P.src[1] = Hbuf; P.src[2] = nuclei;
    P.Z = Zbuf;
    edge_mma<<<444, 512, EDGE_SMEM>>>(P);

    // out = electrons + Zcat @ [g_same; g_anti; g_n]
    gemm_mma<<<dim3(4, 64), 256, GEMM_SMEM>>>(Zbuf, 768, gcs, gcs + 3 * KER * EMB,
                                              electrons, (float*)d_out);
}